// round 10
// baseline (speedup 1.0000x reference)
#include <cuda_runtime.h>

#define H 28
#define W 28
#define NSQ (H * W)          // 784 pixels
#define NE_H (H * (W - 1))   // 756
#define NE_V ((H - 1) * W)   // 756
#define NE_B (2 * H + 2 * W) // 112
#define NE (NE_H + NE_V + NE_B) // 1624
#define NT 256               // threads per block (8 warps)
#define KMAX 1024
#define HSZ 1024
#define PMAX 512             // max dense nodes (peaks + outer); true max 393
#define CARD 50
#define EMPTY64 0xFFFFFFFFFFFFFFFFull

__device__ __forceinline__ unsigned monof(float x) {
    unsigned u = __float_as_uint(x);
    return (u & 0x80000000u) ? ~u : (u | 0x80000000u);
}
__device__ __forceinline__ float invmonof(unsigned m) {
    return __uint_as_float((m & 0x80000000u) ? (m ^ 0x80000000u) : ~m);
}

__global__ __launch_bounds__(NT, 1)
void cubical_kernel(const float* __restrict__ I, const float* __restrict__ p,
                    float* __restrict__ out) {
    __shared__ float Ip[NSQ];
    __shared__ short g[NSQ];                    // ascent ptr -> (then) peak
    __shared__ short lbl[NSQ];                  // peak pixel -> dense id
    __shared__ unsigned long long key[KMAX];    // deduped edges / sort buffer
    __shared__ unsigned long long scratch[HSZ]; // hash -> mst list -> pw/pd
    __shared__ int   parent[PMAX];
    __shared__ float cmaxv[PMAX];
    __shared__ unsigned long long best[PMAX];
    __shared__ int cnt_peaks, ecnt, nmst, npairs, roundun, smem_M;

    const int t = threadIdx.x;
    const int lane = t & 31;
    const int warp = t >> 5;
    const float p0 = p[0], p1 = p[1];

    // ---- Phase 1: Ip = I.p, init ----
    for (int i = t; i < NSQ; i += NT)
        Ip[i] = fmaf(I[2 * i], p0, I[2 * i + 1] * p1);
    if (t == 0) { cnt_peaks = 0; ecnt = 0; nmst = 0; npairs = 0; }
    for (int i = t; i < HSZ; i += NT) scratch[i] = EMPTY64;
    for (int i = t; i < PMAX; i += NT) { parent[i] = i; best[i] = 0ull; }
    __syncthreads();

    // ---- Phase 2: steepest-ascent pointer ----
    for (int i = t; i < NSQ; i += NT) {
        const int row = i / W, col = i - row * W;
        float bf = Ip[i]; int bid = i;
        if (col > 0)     { float f = Ip[i - 1]; if (f > bf) { bf = f; bid = i - 1; } }
        if (col < W - 1) { float f = Ip[i + 1]; if (f > bf) { bf = f; bid = i + 1; } }
        if (row > 0)     { float f = Ip[i - W]; if (f > bf) { bf = f; bid = i - W; } }
        if (row < H - 1) { float f = Ip[i + W]; if (f > bf) { bf = f; bid = i + W; } }
        g[i] = (short)bid;
    }
    __syncthreads();

    // ---- Phase 3: register chase to peak (read-only, ascent forest: acyclic) ----
    {
        short gf[4]; int c = 0;
        for (int i = t; i < NSQ; i += NT) {
            int x = i, gx = g[x];
            while (gx != x) { x = gx; gx = g[x]; }
            gf[c++] = (short)x;
        }
        __syncthreads();
        c = 0;
        for (int i = t; i < NSQ; i += NT) g[i] = gf[c++];
    }
    __syncthreads();

    // ---- Phase 3.5: dense relabel of peaks ----
    for (int i = t; i < NSQ; i += NT) {
        if (g[i] == (short)i) {
            int id = atomicAdd(&cnt_peaks, 1);
            lbl[i] = (short)id;
            cmaxv[id] = Ip[i];
        }
    }
    __syncthreads();
    const int P = cnt_peaks;      // outer id = P
    const int NND = P + 1;
    if (t == 0) cmaxv[P] = 3.0e38f;
    __syncthreads();

    // ---- Phase 4: hash dedup (max weight per peak pair) ----
    for (int i = t; i < NE; i += NT) {
        int pu, pv; float w;
        if (i < NE_H) {
            int r = i / (W - 1), c = i % (W - 1);
            int u = r * W + c, v = u + 1;
            w = fminf(Ip[u], Ip[v]);
            pu = lbl[g[u]]; pv = lbl[g[v]];
        } else if (i < NE_H + NE_V) {
            int j = i - NE_H;
            int u = j, v = j + W;
            w = fminf(Ip[u], Ip[v]);
            pu = lbl[g[u]]; pv = lbl[g[v]];
        } else {
            int j = i - NE_H - NE_V;
            int sq;
            if (j < W)              sq = j;
            else if (j < 2 * W)     sq = (H - 1) * W + (j - W);
            else if (j < 2 * W + H) sq = (j - 2 * W) * W;
            else                    sq = (j - 2 * W - H) * W + (W - 1);
            w = Ip[sq];
            pu = lbl[g[sq]]; pv = P;
        }
        if (pu != pv) {
            int pmin = pu < pv ? pu : pv;
            int pmax = pu < pv ? pv : pu;
            unsigned pair = ((unsigned)pmin << 10) | (unsigned)pmax;
            unsigned long long desired = ((unsigned long long)monof(w) << 20) | pair;
            unsigned s = (pair * 2654435761u) & (HSZ - 1);
            for (;;) {
                unsigned long long cur = scratch[s];
                if (cur == EMPTY64) {
                    unsigned long long old = atomicCAS(&scratch[s], EMPTY64, desired);
                    if (old == EMPTY64) break;
                    cur = old;
                }
                if ((unsigned)(cur & 0xFFFFFu) == pair) {
                    atomicMax(&scratch[s], desired);
                    break;
                }
                s = (s + 1) & (HSZ - 1);
            }
        }
    }
    __syncthreads();

    // ---- Phase 4.5: compact hash -> key[] (format wm<<20|pair) ----
    for (int i = t; i < HSZ; i += NT) {
        unsigned long long e = scratch[i];
        if (e != EMPTY64) {
            int idx = atomicAdd(&ecnt, 1);
            key[idx] = e;
        }
    }
    __syncthreads();
    const int EC = ecnt;

    // ---- Phase 5: Boruvka max-spanning-tree ----
    // Deposit chases roots on a STABLE parent array and stores the ROOT pair
    // in the offer; hook then needs no chase (avoids R9's transient-cycle hang).
    for (int round = 0; round < 12; round++) {
        for (int i = t; i < EC; i += NT) {
            unsigned long long e = key[i];
            unsigned wmv = (unsigned)(e >> 20);
            unsigned pr = (unsigned)(e & 0xFFFFFull);
            int a = (int)(pr >> 10), b = (int)(pr & 1023u);
            int q = parent[a]; while (parent[q] != q) q = parent[q];
            int pa = q;
            q = parent[b]; while (parent[q] != q) q = parent[q];
            int pb = q;
            if (pa != pb) {
                unsigned long long off = ((unsigned long long)wmv << 20) |
                                         ((unsigned)pa << 10) | (unsigned)pb;
                atomicMax(&best[pa], off);
                atomicMax(&best[pb], off);
            }
        }
        if (t == 0) roundun = 0;
        __syncthreads();
        // hook: pure register decode, no parent reads of mutable entries
        for (int i = t; i < NND; i += NT) {
            unsigned long long e = best[i];
            if (e != 0ull && parent[i] == i) {
                int pa = (int)((e >> 10) & 1023ull);
                int pb = (int)(e & 1023ull);
                parent[i] = (pa == i) ? pb : pa;
            }
        }
        __syncthreads();
        // break mutual 2-cycles (smaller id stays root); longer cycles impossible
        for (int i = t; i < NND; i += NT) {
            int pj = parent[i];
            if (pj != i && parent[pj] == i && i < pj) parent[i] = i;
        }
        __syncthreads();
        // commit: surviving hooks emit their MST edge exactly once
        for (int i = t; i < NND; i += NT) {
            unsigned long long e = best[i];
            if (e != 0ull && parent[i] != i) {
                int idx = atomicAdd(&nmst, 1);
                unsigned wm = (unsigned)(e >> 20);
                scratch[idx] = ((unsigned long long)(~wm) << 32) | (e & 0xFFFFFull);
                atomicAdd(&roundun, 1);
            }
            best[i] = 0ull;
        }
        __syncthreads();
        if (roundun == 0) break;
        // one jump round (depth shrink; benign monotone race)
        for (int i = t; i < NND; i += NT) parent[i] = parent[parent[i]];
        __syncthreads();
    }

    // ---- Phase 6: sort MST edges ascending (== weight descending) ----
    if (t == 0) {
        int M = 256;
        while (M < nmst) M <<= 1;
        smem_M = M;
    }
    __syncthreads();
    const int M = smem_M;
    const int nm = nmst;
    for (int i = t; i < M; i += NT)
        key[i] = (i < nm) ? scratch[i] : EMPTY64;
    __syncthreads();
    {
        const bool act = (warp << 6) < M;
        const int i0 = (warp << 6) + lane;
        const int i1 = i0 + 32;
        unsigned long long v0 = 0, v1 = 0;
        const unsigned FULL = 0xffffffffu;
        if (act) {
            v0 = key[i0]; v1 = key[i1];
            #pragma unroll
            for (int k2 = 2; k2 <= 64; k2 <<= 1) {
                if (k2 == 64) {
                    bool up = ((i0 & k2) == 0);
                    if ((v0 > v1) == up) { unsigned long long tm = v0; v0 = v1; v1 = tm; }
                }
                #pragma unroll
                for (int j = (k2 >= 32 ? 16 : (k2 >> 1)); j >= 1; j >>= 1) {
                    unsigned long long q0 = __shfl_xor_sync(FULL, v0, j);
                    unsigned long long q1 = __shfl_xor_sync(FULL, v1, j);
                    bool lower = (lane & j) == 0;
                    bool km0 = (lower == ((i0 & k2) == 0));
                    bool km1 = (lower == ((i1 & k2) == 0));
                    v0 = km0 ? (v0 < q0 ? v0 : q0) : (v0 > q0 ? v0 : q0);
                    v1 = km1 ? (v1 < q1 ? v1 : q1) : (v1 > q1 ? v1 : q1);
                }
            }
            key[i0] = v0; key[i1] = v1;
        }
        __syncthreads();
        for (int k2 = 128; k2 <= M; k2 <<= 1) {
            for (int j = k2 >> 1; j >= 64; j >>= 1) {
                for (int tt = t; tt < (M >> 1); tt += NT) {
                    int l = ((tt & ~(j - 1)) << 1) | (tt & (j - 1));
                    int m = l | j;
                    unsigned long long kl = key[l], km = key[m];
                    bool asc = ((l & k2) == 0);
                    if ((kl > km) == asc) { key[l] = km; key[m] = kl; }
                }
                __syncthreads();
            }
            if (act) {
                v0 = key[i0]; v1 = key[i1];
                {
                    bool up = ((i0 & k2) == 0);
                    if ((v0 > v1) == up) { unsigned long long tm = v0; v0 = v1; v1 = tm; }
                }
                #pragma unroll
                for (int j = 16; j >= 1; j >>= 1) {
                    unsigned long long q0 = __shfl_xor_sync(FULL, v0, j);
                    unsigned long long q1 = __shfl_xor_sync(FULL, v1, j);
                    bool lower = (lane & j) == 0;
                    bool km0 = (lower == ((i0 & k2) == 0));
                    bool km1 = (lower == ((i1 & k2) == 0));
                    v0 = km0 ? (v0 < q0 ? v0 : q0) : (v0 > q0 ? v0 : q0);
                    v1 = km1 ? (v1 < q1 ? v1 : q1) : (v1 > q1 ? v1 : q1);
                }
                key[i0] = v0; key[i1] = v1;
            }
            __syncthreads();
        }
    }

    // ---- Phase 7: serial elder-rule scan over sorted MST edges ----
    float* pwv = (float*)scratch;            // mst list dead after copy
    float* pdv = ((float*)scratch) + PMAX;
    for (int i = t; i < PMAX; i += NT) parent[i] = i;
    __syncthreads();
    if (t == 0) {
        int np = 0;
        #pragma unroll 1
        for (int k = 0; k < M; k++) {
            unsigned long long kk = key[k];
            unsigned wm = (unsigned)(kk >> 32);
            if (wm == 0xFFFFFFFFu) break;
            int a = (int)((kk >> 10) & 1023ull);
            int b = (int)(kk & 1023ull);
            int x = a, px = parent[x];
            while (px != x) { x = px; px = parent[x]; }
            int y = b, py = parent[y];
            while (py != y) { y = py; py = parent[y]; }
            if (x == y) continue;
            float w = invmonof(~wm);
            float Ma = cmaxv[x], Mb = cmaxv[y];
            float die = fminf(Ma, Mb);
            if (die > w) { pwv[np] = w; pdv[np] = die; np++; }
            int win, lose;
            if (Ma >= Mb) { win = x; lose = y; }
            else          { win = y; lose = x; }
            parent[lose] = win;
            parent[a] = win; parent[b] = win;
        }
        npairs = np;
    }
    __syncthreads();

    // ---- Phase 8: rank pairs by persistence desc, emit top CARD, pad ----
    const int np = npairs;
    for (int i = t; i < np; i += NT) {
        float pi = pdv[i] - pwv[i];
        int rank = 0;
        for (int j = 0; j < np; j++) {
            float pj = pdv[j] - pwv[j];
            rank += (pj > pi) || (pj == pi && j > i);
        }
        if (rank < CARD) {
            out[2 * rank]     = pwv[i];
            out[2 * rank + 1] = pdv[i];
        }
    }
    float pad = Ip[0];
    for (int k = t; k < CARD; k += NT) {
        if (k >= np) {
            out[2 * k]     = pad;
            out[2 * k + 1] = pad;
        }
    }
}

extern "C" void kernel_launch(void* const* d_in, const int* in_sizes, int n_in,
                              void* d_out, int out_size) {
    const float* I = (const float*)d_in[0];   // (28,28,2) float32
    const float* p = (const float*)d_in[1];   // (2,1) float32
    float* out = (float*)d_out;               // 100 float32
    (void)in_sizes; (void)n_in; (void)out_size;
    cubical_kernel<<<1, NT>>>(I, p, out);
}

// round 11
// speedup vs baseline: 1.1447x; 1.1447x over previous
#include <cuda_runtime.h>

#define H 28
#define W 28
#define NSQ (H * W)          // 784 pixels
#define NE_H (H * (W - 1))   // 756
#define NE_V ((H - 1) * W)   // 756
#define NE_B (2 * H + 2 * W) // 112
#define NE (NE_H + NE_V + NE_B) // 1624
#define NT 1024
#define KMAX 1024
#define HSZ 1024
#define PMAX 512             // max dense nodes (peaks + outer); true max 393
#define CARD 50
#define EMPTY64 0xFFFFFFFFFFFFFFFFull

__device__ __forceinline__ unsigned monof(float x) {
    unsigned u = __float_as_uint(x);
    return (u & 0x80000000u) ? ~u : (u | 0x80000000u);
}
__device__ __forceinline__ float invmonof(unsigned m) {
    return __uint_as_float((m & 0x80000000u) ? (m ^ 0x80000000u) : ~m);
}

__global__ __launch_bounds__(NT, 1)
void cubical_kernel(const float* __restrict__ I, const float* __restrict__ p,
                    float* __restrict__ out) {
    __shared__ float Ip[NSQ];
    __shared__ short g[NSQ];                    // ascent ptr -> (then) peak
    __shared__ short lbl[NSQ];                  // peak pixel -> dense id
    __shared__ unsigned long long key[KMAX];    // deduped edges / sort buffer
    __shared__ unsigned long long scratch[HSZ]; // hash -> mst list -> pw/pd
    __shared__ int   parent[PMAX];
    __shared__ float cmaxv[PMAX];
    __shared__ unsigned long long best[PMAX];
    __shared__ int cnt_peaks, ecnt, nmst, npairs, roundun, smem_M;

    const int t = threadIdx.x;
    const int lane = t & 31;
    const int warp = t >> 5;
    const float p0 = p[0], p1 = p[1];

    // ---- Phase 1: Ip = I.p, init ----
    if (t < NSQ) Ip[t] = fmaf(I[2 * t], p0, I[2 * t + 1] * p1);
    if (t == 0) { cnt_peaks = 0; ecnt = 0; nmst = 0; npairs = 0; }
    if (t < HSZ) scratch[t] = EMPTY64;
    if (t < PMAX) { parent[t] = t; best[t] = 0ull; }
    __syncthreads();

    // ---- Phase 2: steepest-ascent pointer ----
    if (t < NSQ) {
        const int row = t / W, col = t - row * W;
        float bf = Ip[t]; int bid = t;
        if (col > 0)     { float f = Ip[t - 1]; if (f > bf) { bf = f; bid = t - 1; } }
        if (col < W - 1) { float f = Ip[t + 1]; if (f > bf) { bf = f; bid = t + 1; } }
        if (row > 0)     { float f = Ip[t - W]; if (f > bf) { bf = f; bid = t - W; } }
        if (row < H - 1) { float f = Ip[t + W]; if (f > bf) { bf = f; bid = t + W; } }
        g[t] = (short)bid;
    }
    __syncthreads();

    // ---- Phase 3: register chase to peak (read-only ascent forest: acyclic) ----
    short gfin = 0;
    if (t < NSQ) {
        int x = t, gx = g[x];
        while (gx != x) { x = gx; gx = g[x]; }
        gfin = (short)x;
    }
    __syncthreads();
    if (t < NSQ) g[t] = gfin;
    __syncthreads();

    // ---- Phase 3.5: dense relabel of peaks ----
    if (t < NSQ && g[t] == (short)t) {
        int id = atomicAdd(&cnt_peaks, 1);
        lbl[t] = (short)id;
        cmaxv[id] = Ip[t];
    }
    __syncthreads();
    const int P = cnt_peaks;      // outer id = P
    const int NND = P + 1;
    if (t == 0) cmaxv[P] = 3.0e38f;
    __syncthreads();

    // ---- Phase 4: hash dedup (max weight per peak pair) ----
    for (int i = t; i < NE; i += NT) {
        int pu, pv; float w;
        if (i < NE_H) {
            int r = i / (W - 1), c = i % (W - 1);
            int u = r * W + c, v = u + 1;
            w = fminf(Ip[u], Ip[v]);
            pu = lbl[g[u]]; pv = lbl[g[v]];
        } else if (i < NE_H + NE_V) {
            int j = i - NE_H;
            int u = j, v = j + W;
            w = fminf(Ip[u], Ip[v]);
            pu = lbl[g[u]]; pv = lbl[g[v]];
        } else {
            int j = i - NE_H - NE_V;
            int sq;
            if (j < W)              sq = j;
            else if (j < 2 * W)     sq = (H - 1) * W + (j - W);
            else if (j < 2 * W + H) sq = (j - 2 * W) * W;
            else                    sq = (j - 2 * W - H) * W + (W - 1);
            w = Ip[sq];
            pu = lbl[g[sq]]; pv = P;
        }
        if (pu != pv) {
            int pmin = pu < pv ? pu : pv;
            int pmax = pu < pv ? pv : pu;
            unsigned pair = ((unsigned)pmin << 10) | (unsigned)pmax;
            unsigned long long desired = ((unsigned long long)monof(w) << 20) | pair;
            unsigned s = (pair * 2654435761u) & (HSZ - 1);
            for (;;) {
                unsigned long long cur = scratch[s];
                if (cur == EMPTY64) {
                    unsigned long long old = atomicCAS(&scratch[s], EMPTY64, desired);
                    if (old == EMPTY64) break;
                    cur = old;
                }
                if ((unsigned)(cur & 0xFFFFFu) == pair) {
                    atomicMax(&scratch[s], desired);
                    break;
                }
                s = (s + 1) & (HSZ - 1);
            }
        }
    }
    __syncthreads();

    // ---- Phase 4.5: compact hash -> key[] (format wm<<20|pair) ----
    if (t < HSZ) {
        unsigned long long e = scratch[t];
        if (e != EMPTY64) {
            int idx = atomicAdd(&ecnt, 1);
            key[idx] = e;
        }
    }
    __syncthreads();
    const int EC = ecnt;

    // ---- Phase 5: Boruvka max-spanning-tree ----
    // deposit chases roots on a STABLE parent array and stores the ROOT pair
    // in the offer; hook is pure register decode (no concurrent-chase hang).
    for (int round = 0; round < 12; round++) {
        if (t < EC) {
            unsigned long long e = key[t];
            unsigned wmv = (unsigned)(e >> 20);
            unsigned pr = (unsigned)(e & 0xFFFFFull);
            int a = (int)(pr >> 10), b = (int)(pr & 1023u);
            int q = parent[a]; while (parent[q] != q) q = parent[q];
            int pa = q;
            q = parent[b]; while (parent[q] != q) q = parent[q];
            int pb = q;
            if (pa != pb) {
                unsigned long long off = ((unsigned long long)wmv << 20) |
                                         ((unsigned)pa << 10) | (unsigned)pb;
                atomicMax(&best[pa], off);
                atomicMax(&best[pb], off);
            }
        }
        if (t == 0) roundun = 0;
        __syncthreads();
        if (t < NND) {
            unsigned long long e = best[t];
            if (e != 0ull && parent[t] == t) {
                int pa = (int)((e >> 10) & 1023ull);
                int pb = (int)(e & 1023ull);
                parent[t] = (pa == t) ? pb : pa;
            }
        }
        __syncthreads();
        // break mutual 2-cycles (smaller id stays root)
        if (t < NND) {
            int pj = parent[t];
            if (pj != t && parent[pj] == t && t < pj) parent[t] = t;
        }
        __syncthreads();
        // commit: surviving hooks emit their MST edge exactly once
        if (t < NND) {
            unsigned long long e = best[t];
            if (e != 0ull && parent[t] != t) {
                int idx = atomicAdd(&nmst, 1);
                unsigned wm = (unsigned)(e >> 20);
                scratch[idx] = ((unsigned long long)(~wm) << 32) | (e & 0xFFFFFull);
                atomicAdd(&roundun, 1);
            }
            best[t] = 0ull;
        }
        __syncthreads();
        if (roundun == 0) break;
        // one jump round (depth shrink; benign monotone race)
        if (t < NND) parent[t] = parent[parent[t]];
        __syncthreads();
    }

    // ---- Phase 6: sort MST edges ascending (== weight descending) ----
    if (t == 0) {
        int M = 256;
        while (M < nmst) M <<= 1;
        smem_M = M;
    }
    __syncthreads();
    const int M = smem_M;
    const int nm = nmst;
    if (t < M) key[t] = (t < nm) ? scratch[t] : EMPTY64;
    __syncthreads();
    {
        const bool act = (warp << 6) < M;
        const int i0 = (warp << 6) + lane;
        const int i1 = i0 + 32;
        unsigned long long v0 = 0, v1 = 0;
        const unsigned FULL = 0xffffffffu;
        if (act) {
            v0 = key[i0]; v1 = key[i1];
            #pragma unroll
            for (int k2 = 2; k2 <= 64; k2 <<= 1) {
                if (k2 == 64) {
                    bool up = ((i0 & k2) == 0);
                    if ((v0 > v1) == up) { unsigned long long tm = v0; v0 = v1; v1 = tm; }
                }
                #pragma unroll
                for (int j = (k2 >= 32 ? 16 : (k2 >> 1)); j >= 1; j >>= 1) {
                    unsigned long long q0 = __shfl_xor_sync(FULL, v0, j);
                    unsigned long long q1 = __shfl_xor_sync(FULL, v1, j);
                    bool lower = (lane & j) == 0;
                    bool km0 = (lower == ((i0 & k2) == 0));
                    bool km1 = (lower == ((i1 & k2) == 0));
                    v0 = km0 ? (v0 < q0 ? v0 : q0) : (v0 > q0 ? v0 : q0);
                    v1 = km1 ? (v1 < q1 ? v1 : q1) : (v1 > q1 ? v1 : q1);
                }
            }
            key[i0] = v0; key[i1] = v1;
        }
        __syncthreads();
        for (int k2 = 128; k2 <= M; k2 <<= 1) {
            for (int j = k2 >> 1; j >= 64; j >>= 1) {
                if (t < (M >> 1)) {
                    int l = ((t & ~(j - 1)) << 1) | (t & (j - 1));
                    int m = l | j;
                    unsigned long long kl = key[l], km = key[m];
                    bool asc = ((l & k2) == 0);
                    if ((kl > km) == asc) { key[l] = km; key[m] = kl; }
                }
                __syncthreads();
            }
            if (act) {
                v0 = key[i0]; v1 = key[i1];
                {
                    bool up = ((i0 & k2) == 0);
                    if ((v0 > v1) == up) { unsigned long long tm = v0; v0 = v1; v1 = tm; }
                }
                #pragma unroll
                for (int j = 16; j >= 1; j >>= 1) {
                    unsigned long long q0 = __shfl_xor_sync(FULL, v0, j);
                    unsigned long long q1 = __shfl_xor_sync(FULL, v1, j);
                    bool lower = (lane & j) == 0;
                    bool km0 = (lower == ((i0 & k2) == 0));
                    bool km1 = (lower == ((i1 & k2) == 0));
                    v0 = km0 ? (v0 < q0 ? v0 : q0) : (v0 > q0 ? v0 : q0);
                    v1 = km1 ? (v1 < q1 ? v1 : q1) : (v1 > q1 ? v1 : q1);
                }
                key[i0] = v0; key[i1] = v1;
            }
            __syncthreads();
        }
    }

    // ---- Phase 7: serial elder-rule scan over sorted MST edges ----
    float* pwv = (float*)scratch;            // mst list dead after copy
    float* pdv = ((float*)scratch) + PMAX;
    if (t < PMAX) parent[t] = t;
    __syncthreads();
    if (t == 0) {
        int np = 0;
        #pragma unroll 1
        for (int k = 0; k < M; k++) {
            unsigned long long kk = key[k];
            unsigned wm = (unsigned)(kk >> 32);
            if (wm == 0xFFFFFFFFu) break;
            int a = (int)((kk >> 10) & 1023ull);
            int b = (int)(kk & 1023ull);
            int x = a, px = parent[x];
            while (px != x) { x = px; px = parent[x]; }
            int y = b, py = parent[y];
            while (py != y) { y = py; py = parent[y]; }
            if (x == y) continue;
            float w = invmonof(~wm);
            float Ma = cmaxv[x], Mb = cmaxv[y];
            float die = fminf(Ma, Mb);
            if (die > w) { pwv[np] = w; pdv[np] = die; np++; }
            int win, lose;
            if (Ma >= Mb) { win = x; lose = y; }
            else          { win = y; lose = x; }
            parent[lose] = win;
            parent[a] = win; parent[b] = win;
        }
        npairs = np;
    }
    __syncthreads();

    // ---- Phase 8: rank pairs by persistence desc, emit top CARD, pad ----
    const int np = npairs;
    if (t < np) {
        float pi = pdv[t] - pwv[t];
        int rank = 0;
        for (int j = 0; j < np; j++) {
            float pj = pdv[j] - pwv[j];
            rank += (pj > pi) || (pj == pi && j > t);
        }
        if (rank < CARD) {
            out[2 * rank]     = pwv[t];
            out[2 * rank + 1] = pdv[t];
        }
    }
    if (t < CARD && t >= np) {
        float pad = Ip[0];
        out[2 * t]     = pad;
        out[2 * t + 1] = pad;
    }
}

extern "C" void kernel_launch(void* const* d_in, const int* in_sizes, int n_in,
                              void* d_out, int out_size) {
    const float* I = (const float*)d_in[0];   // (28,28,2) float32
    const float* p = (const float*)d_in[1];   // (2,1) float32
    float* out = (float*)d_out;               // 100 float32
    (void)in_sizes; (void)n_in; (void)out_size;
    cubical_kernel<<<1, NT>>>(I, p, out);
}

// round 12
// speedup vs baseline: 1.2839x; 1.1216x over previous
#include <cuda_runtime.h>

#define H 28
#define W 28
#define NSQ (H * W)          // 784 pixels
#define NE_H (H * (W - 1))   // 756
#define NE_V ((H - 1) * W)   // 756
#define NE_B (2 * H + 2 * W) // 112
#define NE (NE_H + NE_V + NE_B) // 1624
#define NT 1024
#define KMAX 1024
#define HSZ 1024
#define PMAX 512             // max dense nodes (peaks + outer); true max 393
#define CARD 50
#define EMPTY64 0xFFFFFFFFFFFFFFFFull

__device__ __forceinline__ unsigned monof(float x) {
    unsigned u = __float_as_uint(x);
    return (u & 0x80000000u) ? ~u : (u | 0x80000000u);
}
__device__ __forceinline__ float invmonof(unsigned m) {
    return __uint_as_float((m & 0x80000000u) ? (m ^ 0x80000000u) : ~m);
}

__global__ __launch_bounds__(NT, 1)
void cubical_kernel(const float* __restrict__ I, const float* __restrict__ p,
                    float* __restrict__ out) {
    __shared__ float Ip[NSQ];
    __shared__ short g[NSQ];                    // ascent ptr -> peak -> dense id
    __shared__ short lbl[NSQ];                  // peak pixel -> dense id
    __shared__ unsigned long long key[KMAX];    // deduped edges / sort buffer
    __shared__ unsigned long long scratch[HSZ]; // hash -> mst list -> pw/pd
    __shared__ int   parent[PMAX];              // Boruvka UF
    __shared__ float cmaxv[PMAX];
    __shared__ unsigned long long best[PMAX];
    __shared__ int2  node2[PMAX];               // scan UF: .x parent, .y cmax bits
    __shared__ int cnt_peaks, ecnt, nmst, npairs, roundun, smem_M;

    const int t = threadIdx.x;
    const int lane = t & 31;
    const int warp = t >> 5;
    const float p0 = p[0], p1 = p[1];

    // ---- Phase 1: Ip = I.p, init ----
    if (t < NSQ) Ip[t] = fmaf(I[2 * t], p0, I[2 * t + 1] * p1);
    if (t == 0) { cnt_peaks = 0; ecnt = 0; nmst = 0; npairs = 0; roundun = 0; }
    if (t < HSZ) scratch[t] = EMPTY64;
    if (t < PMAX) { parent[t] = t; best[t] = 0ull; }
    __syncthreads();

    // ---- Phase 2: steepest-ascent pointer ----
    if (t < NSQ) {
        const int row = t / W, col = t - row * W;
        float bf = Ip[t]; int bid = t;
        if (col > 0)     { float f = Ip[t - 1]; if (f > bf) { bf = f; bid = t - 1; } }
        if (col < W - 1) { float f = Ip[t + 1]; if (f > bf) { bf = f; bid = t + 1; } }
        if (row > 0)     { float f = Ip[t - W]; if (f > bf) { bf = f; bid = t - W; } }
        if (row < H - 1) { float f = Ip[t + W]; if (f > bf) { bf = f; bid = t + W; } }
        g[t] = (short)bid;
    }
    __syncthreads();

    // ---- Phase 3: register chase to peak (read-only ascent forest: acyclic) ----
    short gfin = 0;
    if (t < NSQ) {
        int x = t, gx = g[x];
        while (gx != x) { x = gx; gx = g[x]; }
        gfin = (short)x;
    }
    __syncthreads();
    if (t < NSQ) g[t] = gfin;
    __syncthreads();

    // ---- Phase 3.5: dense relabel of peaks ----
    if (t < NSQ && g[t] == (short)t) {
        int id = atomicAdd(&cnt_peaks, 1);
        lbl[t] = (short)id;
        cmaxv[id] = Ip[t];
    }
    __syncthreads();
    const int P = cnt_peaks;      // outer id = P
    const int NND = P + 1;
    if (t == 0) cmaxv[P] = 3.0e38f;
    // rewrite g to dense ids (kills one indirection in the dedup loop)
    short gdense = 0;
    if (t < NSQ) gdense = lbl[g[t]];
    __syncthreads();
    if (t < NSQ) g[t] = gdense;
    __syncthreads();

    // ---- Phase 4: hash dedup (max weight per peak pair) ----
    for (int i = t; i < NE; i += NT) {
        int pu, pv; float w;
        if (i < NE_H) {
            int r = i / (W - 1), c = i % (W - 1);
            int u = r * W + c, v = u + 1;
            w = fminf(Ip[u], Ip[v]);
            pu = g[u]; pv = g[v];
        } else if (i < NE_H + NE_V) {
            int j = i - NE_H;
            int u = j, v = j + W;
            w = fminf(Ip[u], Ip[v]);
            pu = g[u]; pv = g[v];
        } else {
            int j = i - NE_H - NE_V;
            int sq;
            if (j < W)              sq = j;
            else if (j < 2 * W)     sq = (H - 1) * W + (j - W);
            else if (j < 2 * W + H) sq = (j - 2 * W) * W;
            else                    sq = (j - 2 * W - H) * W + (W - 1);
            w = Ip[sq];
            pu = g[sq]; pv = P;
        }
        if (pu != pv) {
            int pmin = pu < pv ? pu : pv;
            int pmax = pu < pv ? pv : pu;
            unsigned pair = ((unsigned)pmin << 10) | (unsigned)pmax;
            unsigned long long desired = ((unsigned long long)monof(w) << 20) | pair;
            unsigned s = (pair * 2654435761u) & (HSZ - 1);
            for (;;) {
                unsigned long long cur = scratch[s];
                if (cur == EMPTY64) {
                    unsigned long long old = atomicCAS(&scratch[s], EMPTY64, desired);
                    if (old == EMPTY64) break;
                    cur = old;
                }
                if ((unsigned)(cur & 0xFFFFFu) == pair) {
                    atomicMax(&scratch[s], desired);
                    break;
                }
                s = (s + 1) & (HSZ - 1);
            }
        }
    }
    __syncthreads();

    // ---- Phase 4.5: compact hash -> key[] AND round-0 deposit (roots = ids) ----
    if (t < HSZ) {
        unsigned long long e = scratch[t];
        if (e != EMPTY64) {
            int idx = atomicAdd(&ecnt, 1);
            key[idx] = e;
            unsigned pr = (unsigned)(e & 0xFFFFFull);
            atomicMax(&best[pr >> 10], e);
            atomicMax(&best[pr & 1023u], e);
        }
    }
    __syncthreads();
    const int EC = ecnt;

    // ---- Phase 5: Boruvka max-spanning-tree ----
    // fused hook+break+commit: parent[i] written only by thread i; mutuality
    // decided from best[] alone (best[i]==best[r] for mutual pairs).
    for (int round = 0; round < 12; round++) {
        if (t < NND) {
            unsigned long long e = best[t];
            if (e != 0ull && parent[t] == t) {
                int pa = (int)((e >> 10) & 1023ull);
                int pb = (int)(e & 1023ull);
                int r = (pa == t) ? pb : pa;
                unsigned long long er = best[r];
                int ra = (int)((er >> 10) & 1023ull);
                int rb = (int)(er & 1023ull);
                int rother = (ra == r) ? rb : ra;
                bool mutual = (rother == t);
                if (!(mutual && t < r)) {
                    parent[t] = r;          // hook (loses 2-cycle tie or chains)
                    int idx = atomicAdd(&nmst, 1);
                    unsigned wm = (unsigned)(e >> 20);
                    scratch[idx] = ((unsigned long long)(~wm) << 32) | (e & 0xFFFFFull);
                    atomicAdd(&roundun, 1);
                }
            }
        }
        __syncthreads();
        if (roundun == 0) break;            // stable until next write phase
        if (t < NND) { parent[t] = parent[parent[t]]; best[t] = 0ull; }
        __syncthreads();
        if (t < NND) parent[t] = parent[parent[t]];
        if (t == 0) roundun = 0;
        __syncthreads();
        // deposit on (now shallow) roots
        if (t < EC) {
            unsigned long long e = key[t];
            unsigned pr = (unsigned)(e & 0xFFFFFull);
            int a = (int)(pr >> 10), b = (int)(pr & 1023u);
            int q = parent[a]; while (parent[q] != q) q = parent[q];
            int pa = q;
            q = parent[b]; while (parent[q] != q) q = parent[q];
            int pb = q;
            if (pa != pb) {
                unsigned long long off = (e & ~0xFFFFFull) |
                                         ((unsigned)pa << 10) | (unsigned)pb;
                atomicMax(&best[pa], off);
                atomicMax(&best[pb], off);
            }
        }
        __syncthreads();
    }

    // ---- Phase 6: sort MST edges ascending (== weight descending) ----
    if (t == 0) {
        int M = 256;
        while (M < nmst) M <<= 1;
        smem_M = M;
    }
    __syncthreads();
    const int M = smem_M;
    const int nm = nmst;
    if (t < M) key[t] = (t < nm) ? scratch[t] : EMPTY64;
    if (t < PMAX) node2[t] = make_int2(t, __float_as_int(cmaxv[t]));  // scan UF init
    __syncthreads();
    {
        const bool act = (warp << 6) < M;
        const int i0 = (warp << 6) + lane;
        const int i1 = i0 + 32;
        unsigned long long v0 = 0, v1 = 0;
        const unsigned FULL = 0xffffffffu;
        if (act) {
            v0 = key[i0]; v1 = key[i1];
            #pragma unroll
            for (int k2 = 2; k2 <= 64; k2 <<= 1) {
                if (k2 == 64) {
                    bool up = ((i0 & k2) == 0);
                    if ((v0 > v1) == up) { unsigned long long tm = v0; v0 = v1; v1 = tm; }
                }
                #pragma unroll
                for (int j = (k2 >= 32 ? 16 : (k2 >> 1)); j >= 1; j >>= 1) {
                    unsigned long long q0 = __shfl_xor_sync(FULL, v0, j);
                    unsigned long long q1 = __shfl_xor_sync(FULL, v1, j);
                    bool lower = (lane & j) == 0;
                    bool km0 = (lower == ((i0 & k2) == 0));
                    bool km1 = (lower == ((i1 & k2) == 0));
                    v0 = km0 ? (v0 < q0 ? v0 : q0) : (v0 > q0 ? v0 : q0);
                    v1 = km1 ? (v1 < q1 ? v1 : q1) : (v1 > q1 ? v1 : q1);
                }
            }
            key[i0] = v0; key[i1] = v1;
        }
        __syncthreads();
        for (int k2 = 128; k2 <= M; k2 <<= 1) {
            for (int j = k2 >> 1; j >= 64; j >>= 1) {
                if (t < (M >> 1)) {
                    int l = ((t & ~(j - 1)) << 1) | (t & (j - 1));
                    int m = l | j;
                    unsigned long long kl = key[l], km = key[m];
                    bool asc = ((l & k2) == 0);
                    if ((kl > km) == asc) { key[l] = km; key[m] = kl; }
                }
                __syncthreads();
            }
            if (act) {
                v0 = key[i0]; v1 = key[i1];
                {
                    bool up = ((i0 & k2) == 0);
                    if ((v0 > v1) == up) { unsigned long long tm = v0; v0 = v1; v1 = tm; }
                }
                #pragma unroll
                for (int j = 16; j >= 1; j >>= 1) {
                    unsigned long long q0 = __shfl_xor_sync(FULL, v0, j);
                    unsigned long long q1 = __shfl_xor_sync(FULL, v1, j);
                    bool lower = (lane & j) == 0;
                    bool km0 = (lower == ((i0 & k2) == 0));
                    bool km1 = (lower == ((i1 & k2) == 0));
                    v0 = km0 ? (v0 < q0 ? v0 : q0) : (v0 > q0 ? v0 : q0);
                    v1 = km1 ? (v1 < q1 ? v1 : q1) : (v1 > q1 ? v1 : q1);
                }
                key[i0] = v0; key[i1] = v1;
            }
            __syncthreads();
        }
    }

    // ---- Phase 7: serial elder-rule scan (packed parent+cmax, 1 LDS.64/hop) ----
    float* pwv = (float*)scratch;            // mst list dead after sort copy
    float* pdv = ((float*)scratch) + PMAX;
    if (t == 0) {
        int np = 0;
        #pragma unroll 1
        for (int k = 0; k < M; k++) {
            unsigned long long kk = key[k];
            unsigned wm = (unsigned)(kk >> 32);
            if (wm == 0xFFFFFFFFu) break;
            int a = (int)((kk >> 10) & 1023ull);
            int b = (int)(kk & 1023ull);
            const int a0 = a, b0 = b;
            int2 ra = node2[a];
            while (ra.x != a) { a = ra.x; ra = node2[a]; }
            int2 rb = node2[b];
            while (rb.x != b) { b = rb.x; rb = node2[b]; }
            float w = invmonof(~wm);
            float Ma = __int_as_float(ra.y), Mb = __int_as_float(rb.y);
            float die = fminf(Ma, Mb);
            if (die > w) { pwv[np] = w; pdv[np] = die; np++; }
            int win, lose;
            if (Ma >= Mb) { win = a; lose = b; }
            else          { win = b; lose = a; }
            node2[lose].x = win;
            node2[a0].x = win;               // compress originals to root
            node2[b0].x = win;
        }
        npairs = np;
    }
    __syncthreads();

    // ---- Phase 8: rank pairs by persistence desc, emit top CARD, pad ----
    const int np = npairs;
    if (t < np) {
        float pi = pdv[t] - pwv[t];
        int rank = 0;
        for (int j = 0; j < np; j++) {
            float pj = pdv[j] - pwv[j];
            rank += (pj > pi) || (pj == pi && j > t);
        }
        if (rank < CARD) {
            out[2 * rank]     = pwv[t];
            out[2 * rank + 1] = pdv[t];
        }
    }
    if (t < CARD && t >= np) {
        float pad = Ip[0];
        out[2 * t]     = pad;
        out[2 * t + 1] = pad;
    }
}

extern "C" void kernel_launch(void* const* d_in, const int* in_sizes, int n_in,
                              void* d_out, int out_size) {
    const float* I = (const float*)d_in[0];   // (28,28,2) float32
    const float* p = (const float*)d_in[1];   // (2,1) float32
    float* out = (float*)d_out;               // 100 float32
    (void)in_sizes; (void)n_in; (void)out_size;
    cubical_kernel<<<1, NT>>>(I, p, out);
}

// round 13
// speedup vs baseline: 1.3622x; 1.0609x over previous
#include <cuda_runtime.h>

#define H 28
#define W 28
#define NSQ (H * W)          // 784 pixels
#define NE_H (H * (W - 1))   // 756
#define NE_V ((H - 1) * W)   // 756
#define NE_B (2 * H + 2 * W) // 112
#define NE (NE_H + NE_V + NE_B) // 1624
#define NT 1024
#define KMAX 1024
#define HSZ 1024
#define PMAX 512             // max dense nodes (peaks + outer); true max 393
#define CARD 50
#define EMPTY64 0xFFFFFFFFFFFFFFFFull

__device__ __forceinline__ unsigned monof(float x) {
    unsigned u = __float_as_uint(x);
    return (u & 0x80000000u) ? ~u : (u | 0x80000000u);
}
__device__ __forceinline__ float invmonof(unsigned m) {
    return __uint_as_float((m & 0x80000000u) ? (m ^ 0x80000000u) : ~m);
}

__global__ __launch_bounds__(NT, 1)
void cubical_kernel(const float* __restrict__ I, const float* __restrict__ p,
                    float* __restrict__ out) {
    __shared__ float Ip[NSQ];
    __shared__ short g[NSQ];                    // ascent ptr -> peak -> dense id
    __shared__ short lbl[NSQ];                  // peak pixel -> dense id
    __shared__ unsigned long long key[KMAX];    // deduped edges / sort buffer
    __shared__ unsigned long long scratch[HSZ]; // hash -> mst list -> pw/pd
    __shared__ int   parent[PMAX];              // Boruvka UF
    __shared__ float cmaxv[PMAX];
    __shared__ unsigned long long best[PMAX];
    __shared__ int2  node2[PMAX];               // scan UF: .x parent, .y cmax bits
    __shared__ int cnt_peaks, ecnt, nmst, npairs, roundun, smem_M;

    const int t = threadIdx.x;
    const int lane = t & 31;
    const int warp = t >> 5;
    const float p0 = p[0], p1 = p[1];

    // ---- Phase 1: Ip = I.p, init ----
    if (t < NSQ) Ip[t] = fmaf(I[2 * t], p0, I[2 * t + 1] * p1);
    if (t == 0) { cnt_peaks = 0; ecnt = 0; nmst = 0; npairs = 0; roundun = 0; }
    if (t < HSZ) scratch[t] = EMPTY64;
    if (t < PMAX) { parent[t] = t; best[t] = 0ull; }
    __syncthreads();

    // ---- Phase 2: steepest-ascent pointer ----
    if (t < NSQ) {
        const int row = t / W, col = t - row * W;
        float bf = Ip[t]; int bid = t;
        if (col > 0)     { float f = Ip[t - 1]; if (f > bf) { bf = f; bid = t - 1; } }
        if (col < W - 1) { float f = Ip[t + 1]; if (f > bf) { bf = f; bid = t + 1; } }
        if (row > 0)     { float f = Ip[t - W]; if (f > bf) { bf = f; bid = t - W; } }
        if (row < H - 1) { float f = Ip[t + W]; if (f > bf) { bf = f; bid = t + W; } }
        g[t] = (short)bid;
    }
    __syncthreads();

    // ---- Phase 3: register chase to peak (read-only ascent forest: acyclic) ----
    short gfin = 0;
    if (t < NSQ) {
        int x = t, gx = g[x];
        while (gx != x) { x = gx; gx = g[x]; }
        gfin = (short)x;
    }
    __syncthreads();
    if (t < NSQ) g[t] = gfin;
    __syncthreads();

    // ---- Phase 3.5: dense relabel of peaks ----
    if (t < NSQ && g[t] == (short)t) {
        int id = atomicAdd(&cnt_peaks, 1);
        lbl[t] = (short)id;
        cmaxv[id] = Ip[t];
    }
    __syncthreads();
    const int P = cnt_peaks;      // outer id = P
    const int NND = P + 1;
    if (t == 0) cmaxv[P] = 3.0e38f;
    short gdense = 0;
    if (t < NSQ) gdense = lbl[g[t]];
    __syncthreads();
    if (t < NSQ) g[t] = gdense;
    __syncthreads();

    // ---- Phase 4: hash dedup (max weight per peak pair) ----
    for (int i = t; i < NE; i += NT) {
        int pu, pv; float w;
        if (i < NE_H) {
            int r = i / (W - 1), c = i % (W - 1);
            int u = r * W + c, v = u + 1;
            w = fminf(Ip[u], Ip[v]);
            pu = g[u]; pv = g[v];
        } else if (i < NE_H + NE_V) {
            int j = i - NE_H;
            int u = j, v = j + W;
            w = fminf(Ip[u], Ip[v]);
            pu = g[u]; pv = g[v];
        } else {
            int j = i - NE_H - NE_V;
            int sq;
            if (j < W)              sq = j;
            else if (j < 2 * W)     sq = (H - 1) * W + (j - W);
            else if (j < 2 * W + H) sq = (j - 2 * W) * W;
            else                    sq = (j - 2 * W - H) * W + (W - 1);
            w = Ip[sq];
            pu = g[sq]; pv = P;
        }
        if (pu != pv) {
            int pmin = pu < pv ? pu : pv;
            int pmax = pu < pv ? pv : pu;
            unsigned pair = ((unsigned)pmin << 10) | (unsigned)pmax;
            unsigned long long desired = ((unsigned long long)monof(w) << 20) | pair;
            unsigned s = (pair * 2654435761u) & (HSZ - 1);
            for (;;) {
                unsigned long long cur = scratch[s];
                if (cur == EMPTY64) {
                    unsigned long long old = atomicCAS(&scratch[s], EMPTY64, desired);
                    if (old == EMPTY64) break;
                    cur = old;
                }
                if ((unsigned)(cur & 0xFFFFFu) == pair) {
                    atomicMax(&scratch[s], desired);
                    break;
                }
                s = (s + 1) & (HSZ - 1);
            }
        }
    }
    __syncthreads();

    // ---- Phase 4.5: compact hash -> key[] AND round-0 deposit (roots = ids) ----
    if (t < HSZ) {
        unsigned long long e = scratch[t];
        if (e != EMPTY64) {
            int idx = atomicAdd(&ecnt, 1);
            key[idx] = e;
            unsigned pr = (unsigned)(e & 0xFFFFFull);
            atomicMax(&best[pr >> 10], e);
            atomicMax(&best[pr & 1023u], e);
        }
    }
    __syncthreads();
    const int EC = ecnt;

    // ---- Phase 5: Boruvka max-spanning-tree ----
    // fused hook+break+commit; deposit relabels key[t] to current root pair
    // (amortized pointer-jumping on edges; internal edges become EMPTY).
    for (int round = 0; round < 12; round++) {
        if (t < NND) {
            unsigned long long e = best[t];
            if (e != 0ull && parent[t] == t) {
                int pa = (int)((e >> 10) & 1023ull);
                int pb = (int)(e & 1023ull);
                int r = (pa == t) ? pb : pa;
                unsigned long long er = best[r];
                int ra = (int)((er >> 10) & 1023ull);
                int rb = (int)(er & 1023ull);
                int rother = (ra == r) ? rb : ra;
                bool mutual = (rother == t);
                if (!(mutual && t < r)) {
                    parent[t] = r;
                    int idx = atomicAdd(&nmst, 1);
                    unsigned wm = (unsigned)(e >> 20);
                    scratch[idx] = ((unsigned long long)(~wm) << 32) | (e & 0xFFFFFull);
                    atomicAdd(&roundun, 1);
                }
            }
        }
        __syncthreads();
        if (roundun == 0) break;
        if (t < NND) { parent[t] = parent[parent[t]]; best[t] = 0ull; }
        __syncthreads();
        if (t < NND) parent[t] = parent[parent[t]];
        if (t == 0) roundun = 0;
        __syncthreads();
        // deposit on shallow roots; relabel edge in place
        if (t < EC) {
            unsigned long long e = key[t];
            if (e != EMPTY64) {
                unsigned pr = (unsigned)(e & 0xFFFFFull);
                int a = (int)(pr >> 10), b = (int)(pr & 1023u);
                int q = parent[a]; while (parent[q] != q) q = parent[q];
                int pa = q;
                q = parent[b]; while (parent[q] != q) q = parent[q];
                int pb = q;
                if (pa != pb) {
                    unsigned long long off = (e & ~0xFFFFFull) |
                                             ((unsigned)pa << 10) | (unsigned)pb;
                    key[t] = off;
                    atomicMax(&best[pa], off);
                    atomicMax(&best[pb], off);
                } else {
                    key[t] = EMPTY64;      // internal: never useful again
                }
            }
        }
        __syncthreads();
    }

    // ---- Phase 6: sort MST edges ascending (== weight descending) ----
    if (t == 0) {
        int M = 256;
        while (M < nmst) M <<= 1;
        smem_M = M;
    }
    __syncthreads();
    const int M = smem_M;
    const int nm = nmst;
    if (t < M) key[t] = (t < nm) ? scratch[t] : EMPTY64;
    if (t < PMAX) node2[t] = make_int2(t, __float_as_int(cmaxv[t]));  // scan UF init
    __syncthreads();
    {
        const bool act = (warp << 6) < M;
        const int i0 = (warp << 6) + lane;
        const int i1 = i0 + 32;
        unsigned long long v0 = 0, v1 = 0;
        const unsigned FULL = 0xffffffffu;
        if (act) {
            v0 = key[i0]; v1 = key[i1];
            #pragma unroll
            for (int k2 = 2; k2 <= 64; k2 <<= 1) {
                if (k2 == 64) {
                    bool up = ((i0 & k2) == 0);
                    if ((v0 > v1) == up) { unsigned long long tm = v0; v0 = v1; v1 = tm; }
                }
                #pragma unroll
                for (int j = (k2 >= 32 ? 16 : (k2 >> 1)); j >= 1; j >>= 1) {
                    unsigned long long q0 = __shfl_xor_sync(FULL, v0, j);
                    unsigned long long q1 = __shfl_xor_sync(FULL, v1, j);
                    bool lower = (lane & j) == 0;
                    bool km0 = (lower == ((i0 & k2) == 0));
                    bool km1 = (lower == ((i1 & k2) == 0));
                    v0 = km0 ? (v0 < q0 ? v0 : q0) : (v0 > q0 ? v0 : q0);
                    v1 = km1 ? (v1 < q1 ? v1 : q1) : (v1 > q1 ? v1 : q1);
                }
            }
            key[i0] = v0; key[i1] = v1;
        }
        __syncthreads();
        for (int k2 = 128; k2 <= M; k2 <<= 1) {
            for (int j = k2 >> 1; j >= 64; j >>= 1) {
                if (t < (M >> 1)) {
                    int l = ((t & ~(j - 1)) << 1) | (t & (j - 1));
                    int m = l | j;
                    unsigned long long kl = key[l], km = key[m];
                    bool asc = ((l & k2) == 0);
                    if ((kl > km) == asc) { key[l] = km; key[m] = kl; }
                }
                __syncthreads();
            }
            if (act) {
                v0 = key[i0]; v1 = key[i1];
                {
                    bool up = ((i0 & k2) == 0);
                    if ((v0 > v1) == up) { unsigned long long tm = v0; v0 = v1; v1 = tm; }
                }
                #pragma unroll
                for (int j = 16; j >= 1; j >>= 1) {
                    unsigned long long q0 = __shfl_xor_sync(FULL, v0, j);
                    unsigned long long q1 = __shfl_xor_sync(FULL, v1, j);
                    bool lower = (lane & j) == 0;
                    bool km0 = (lower == ((i0 & k2) == 0));
                    bool km1 = (lower == ((i1 & k2) == 0));
                    v0 = km0 ? (v0 < q0 ? v0 : q0) : (v0 > q0 ? v0 : q0);
                    v1 = km1 ? (v1 < q1 ? v1 : q1) : (v1 > q1 ? v1 : q1);
                }
                key[i0] = v0; key[i1] = v1;
            }
            __syncthreads();
        }
    }

    // ---- Phase 7: serial elder-rule scan (interleaved chases, prefetch) ----
    float* pwv = (float*)scratch;            // mst list dead after sort copy
    float* pdv = ((float*)scratch) + PMAX;
    if (t == 0) {
        int np = 0;
        unsigned long long kk = key[0];
        #pragma unroll 1
        for (int k = 0; k < M; k++) {
            unsigned long long kk_next = key[k + 1];   // prefetch (pad safe: k+1<=M<KMAX? M can be KMAX... guard below)
            unsigned wm = (unsigned)(kk >> 32);
            if (wm == 0xFFFFFFFFu) break;
            int a = (int)((kk >> 10) & 1023ull);
            int b = (int)(kk & 1023ull);
            const int a0 = a, b0 = b;
            int2 ra = node2[a];
            int2 rb = node2[b];
            bool da = (ra.x == a), db = (rb.x == b);
            while (!(da && db)) {
                if (!da) { a = ra.x; ra = node2[a]; da = (ra.x == a); }
                if (!db) { b = rb.x; rb = node2[b]; db = (rb.x == b); }
            }
            float w = invmonof(~wm);
            float Ma = __int_as_float(ra.y), Mb = __int_as_float(rb.y);
            float die = fminf(Ma, Mb);
            if (die > w) { pwv[np] = w; pdv[np] = die; np++; }
            int win, lose;
            if (Ma >= Mb) { win = a; lose = b; }
            else          { win = b; lose = a; }
            node2[lose].x = win;
            node2[a0].x = win;
            node2[b0].x = win;
            kk = kk_next;
        }
        npairs = np;
    }
    __syncthreads();

    // ---- Phase 8: rank pairs by persistence desc, emit top CARD, pad ----
    const int np = npairs;
    if (t < np) {
        float pi = pdv[t] - pwv[t];
        int rank = 0;
        for (int j = 0; j < np; j++) {
            float pj = pdv[j] - pwv[j];
            rank += (pj > pi) || (pj == pi && j > t);
        }
        if (rank < CARD) {
            out[2 * rank]     = pwv[t];
            out[2 * rank + 1] = pdv[t];
        }
    }
    if (t < CARD && t >= np) {
        float pad = Ip[0];
        out[2 * t]     = pad;
        out[2 * t + 1] = pad;
    }
}

extern "C" void kernel_launch(void* const* d_in, const int* in_sizes, int n_in,
                              void* d_out, int out_size) {
    const float* I = (const float*)d_in[0];   // (28,28,2) float32
    const float* p = (const float*)d_in[1];   // (2,1) float32
    float* out = (float*)d_out;               // 100 float32
    (void)in_sizes; (void)n_in; (void)out_size;
    cubical_kernel<<<1, NT>>>(I, p, out);
}